// round 8
// baseline (speedup 1.0000x reference)
#include <cuda_runtime.h>
#include <cstdint>
#include <cstddef>

// Problem constants
#define B_SZ   4096
#define N_TOK  32
#define H_HEADS 8
#define D_HEAD 64
#define HID    512
#define M_ROWS (B_SZ * N_TOK)   // 131072
#define QKV_COLS (3 * HID)      // 1536

// Scratch (allocation-free rule: __device__ globals)
__device__ float g_qkv[(size_t)M_ROWS * QKV_COLS];  // [131072, 1536]
__device__ float g_ctx[(size_t)M_ROWS * HID];       // [131072, 512]

// ---------------------------------------------------------------------------
// SGEMM: C = A @ B^T + bias.  A:[M,K] rm, B:[N,K] rm.
// BM=BN=128, BK=16; 256 threads; 8x8 micro-tile; double-buffered smem.
// ---------------------------------------------------------------------------
__global__ __launch_bounds__(256) void sgemm_abt(
    const float* __restrict__ A, const float* __restrict__ Bm,
    const float* __restrict__ bias, float* __restrict__ C,
    int M, int N, int K)
{
    constexpr int BM = 128, BN = 128, BK = 16;
    __shared__ float As[2][BK][BM];
    __shared__ float Bs[2][BK][BN];

    const int tid = threadIdx.x;
    const int m0 = blockIdx.y * BM;
    const int n0 = blockIdx.x * BN;

    const int tx = tid & 15;   // 8 cols each
    const int ty = tid >> 4;   // 8 rows each

    const int lr0 = tid >> 2;        // rows 0..63 (+64 for p=1)
    const int lc  = (tid & 3) * 4;   // k-offset 0,4,8,12

    float acc[8][8];
#pragma unroll
    for (int i = 0; i < 8; i++)
#pragma unroll
        for (int j = 0; j < 8; j++) acc[i][j] = 0.f;

    auto load_stage = [&](int buf, int k0) {
#pragma unroll
        for (int p = 0; p < 2; p++) {
            int r = lr0 + 64 * p;
            float4 a = *reinterpret_cast<const float4*>(
                &A[(size_t)(m0 + r) * K + k0 + lc]);
            As[buf][lc + 0][r] = a.x; As[buf][lc + 1][r] = a.y;
            As[buf][lc + 2][r] = a.z; As[buf][lc + 3][r] = a.w;
            float4 b = *reinterpret_cast<const float4*>(
                &Bm[(size_t)(n0 + r) * K + k0 + lc]);
            Bs[buf][lc + 0][r] = b.x; Bs[buf][lc + 1][r] = b.y;
            Bs[buf][lc + 2][r] = b.z; Bs[buf][lc + 3][r] = b.w;
        }
    };

    load_stage(0, 0);
    __syncthreads();

    const int nsteps = K / BK;
    for (int step = 0; step < nsteps; step++) {
        int buf = step & 1;
        if (step + 1 < nsteps) load_stage(buf ^ 1, (step + 1) * BK);

#pragma unroll
        for (int kk = 0; kk < BK; kk++) {
            float ar[8], br[8];
            float4 a0 = *reinterpret_cast<const float4*>(&As[buf][kk][ty * 8]);
            float4 a1 = *reinterpret_cast<const float4*>(&As[buf][kk][ty * 8 + 4]);
            float4 b0 = *reinterpret_cast<const float4*>(&Bs[buf][kk][tx * 8]);
            float4 b1 = *reinterpret_cast<const float4*>(&Bs[buf][kk][tx * 8 + 4]);
            ar[0]=a0.x; ar[1]=a0.y; ar[2]=a0.z; ar[3]=a0.w;
            ar[4]=a1.x; ar[5]=a1.y; ar[6]=a1.z; ar[7]=a1.w;
            br[0]=b0.x; br[1]=b0.y; br[2]=b0.z; br[3]=b0.w;
            br[4]=b1.x; br[5]=b1.y; br[6]=b1.z; br[7]=b1.w;
#pragma unroll
            for (int i = 0; i < 8; i++)
#pragma unroll
                for (int j = 0; j < 8; j++)
                    acc[i][j] = fmaf(ar[i], br[j], acc[i][j]);
        }
        __syncthreads();
    }

    float bv[8];
#pragma unroll
    for (int j = 0; j < 8; j++) bv[j] = bias[n0 + tx * 8 + j];

#pragma unroll
    for (int i = 0; i < 8; i++) {
        size_t row = (size_t)(m0 + ty * 8 + i);
        float4 o0 = make_float4(acc[i][0] + bv[0], acc[i][1] + bv[1],
                                acc[i][2] + bv[2], acc[i][3] + bv[3]);
        float4 o1 = make_float4(acc[i][4] + bv[4], acc[i][5] + bv[5],
                                acc[i][6] + bv[6], acc[i][7] + bv[7]);
        *reinterpret_cast<float4*>(&C[row * N + n0 + tx * 8])     = o0;
        *reinterpret_cast<float4*>(&C[row * N + n0 + tx * 8 + 4]) = o1;
    }
}

// ---------------------------------------------------------------------------
// Attention: one block per (b, h). q,k,v [32,64] from g_qkv, masked softmax,
// attn probs -> d_out tail, ctx -> g_ctx.
// qkv row layout: col = s*512 + h*64 + d  (s = 0:q, 1:k, 2:v)
//
// Mask transport dtype is unknown (bool may be uploaded as uint8, int32 or
// float32). Detect on device via the diagonal invariant mask[i][i]==true:
//   uint8  : byte  [i*33] == 1        for all i in 0..31   (within 1024 B)
//   int32  : int   [i*33] == 1        for i in 0..7        (within 1024 B)
//   float32: float [i*33] == 1.0f     for i in 0..7        (within 1024 B)
// These signatures are mutually exclusive.
// ---------------------------------------------------------------------------
__global__ __launch_bounds__(128) void attn_kernel(
    const float* __restrict__ qkv, const void* __restrict__ mask_raw,
    float* __restrict__ attn_out, float* __restrict__ ctx)
{
    const int bh = blockIdx.x;
    const int b = bh >> 3, h = bh & 7;

    __shared__ float q[32][64], k[32][64], v[32][64];
    __shared__ float s[32][33];
    __shared__ unsigned char msk[1024];
    __shared__ int mode;

    const int tid = threadIdx.x;

    if (tid == 0) {
        const unsigned char* m8 = (const unsigned char*)mask_raw;
        const int* m32 = (const int*)mask_raw;
        bool u8ok = true;
#pragma unroll
        for (int i = 0; i < 32; i++) u8ok &= (m8[i * 33] == 1);
        if (u8ok) { mode = 0; }
        else {
            bool i32ok = true;
#pragma unroll
            for (int i = 0; i < 8; i++) i32ok &= (m32[i * 33] == 1);
            mode = i32ok ? 1 : 2;
        }
    }

    const float* base = qkv + (size_t)b * (N_TOK * QKV_COLS) + h * D_HEAD;
    for (int i = tid; i < 512; i += 128) {
        int n = i >> 4, d4 = (i & 15) * 4;
        const float* rp = base + (size_t)n * QKV_COLS + d4;
        *reinterpret_cast<float4*>(&q[n][d4]) =
            *reinterpret_cast<const float4*>(rp);
        *reinterpret_cast<float4*>(&k[n][d4]) =
            *reinterpret_cast<const float4*>(rp + HID);
        *reinterpret_cast<float4*>(&v[n][d4]) =
            *reinterpret_cast<const float4*>(rp + 2 * HID);
    }
    __syncthreads();

    // decode mask into smem bytes
    {
        int md = mode;
        const unsigned char* m8 = (const unsigned char*)mask_raw;
        const int* m32 = (const int*)mask_raw;
        const float* mf = (const float*)mask_raw;
        for (int i = tid; i < 1024; i += 128) {
            unsigned char mv;
            if (md == 0)      mv = (m8[i] != 0);
            else if (md == 1) mv = (m32[i] != 0);
            else              mv = (mf[i] != 0.0f);
            msk[i] = mv;
        }
    }
    __syncthreads();

    // scores
    for (int e = tid; e < 1024; e += 128) {
        int i = e >> 5, j = e & 31;
        float acc = 0.f;
#pragma unroll
        for (int d = 0; d < 64; d++) acc = fmaf(q[i][d], k[j][d], acc);
        s[i][j] = msk[e] ? acc * 0.125f : -1e9f;
    }
    __syncthreads();

    // softmax (one thread per row)
    if (tid < 32) {
        int i = tid;
        float mx = -3.0e38f;
#pragma unroll
        for (int j = 0; j < 32; j++) mx = fmaxf(mx, s[i][j]);
        float p[32];
        float sum = 0.f;
#pragma unroll
        for (int j = 0; j < 32; j++) { p[j] = expf(s[i][j] - mx); sum += p[j]; }
        float inv = 1.0f / sum;
#pragma unroll
        for (int j = 0; j < 32; j++) s[i][j] = p[j] * inv;
    }
    __syncthreads();

    float* aout = attn_out + (size_t)bh * 1024;
    for (int e = tid; e < 1024; e += 128) aout[e] = s[e >> 5][e & 31];

    // ctx = attn @ v
    float* cbase = ctx + (size_t)b * (N_TOK * HID) + h * D_HEAD;
    for (int e = tid; e < 2048; e += 128) {
        int n = e >> 6, d = e & 63;
        float acc = 0.f;
#pragma unroll
        for (int m = 0; m < 32; m++) acc = fmaf(s[n][m], v[m][d], acc);
        cbase[(size_t)n * HID + d] = acc;
    }
}

// ---------------------------------------------------------------------------
// Inputs (metadata order): module_states f32 [4096,32,512], sparse_mask
// [32,32] (dtype detected on device), Wqkv f32 [1536,512], bqkv f32 [1536],
// Wo f32 [512,512], bo f32 [512]
// Output: output [4096,32,512] floats, then attn [4096,8,32,32].
// ---------------------------------------------------------------------------
extern "C" void kernel_launch(void* const* d_in, const int* in_sizes, int n_in,
                              void* d_out, int out_size)
{
    const float* x    = (const float*)d_in[0];
    const void*  mask = d_in[1];
    const float* Wqkv = (const float*)d_in[2];
    const float* bqkv = (const float*)d_in[3];
    const float* Wo   = (const float*)d_in[4];
    const float* bo   = (const float*)d_in[5];

    float* out  = (float*)d_out;                         // [131072, 512]
    float* attn = out + (size_t)M_ROWS * HID;            // [4096, 8, 32, 32]

    float* qkv_ptr = nullptr;
    float* ctx_ptr = nullptr;
    cudaGetSymbolAddress((void**)&qkv_ptr, g_qkv);
    cudaGetSymbolAddress((void**)&ctx_ptr, g_ctx);

    // 1) QKV = X @ Wqkv^T + bqkv      [131072, 1536]
    {
        dim3 grid(QKV_COLS / 128, M_ROWS / 128);   // (12, 1024)
        sgemm_abt<<<grid, 256>>>(x, Wqkv, bqkv, qkv_ptr, M_ROWS, QKV_COLS, HID);
    }

    // 2) attention per (b, h)
    attn_kernel<<<B_SZ * H_HEADS, 128>>>(qkv_ptr, mask, attn, ctx_ptr);

    // 3) output = ctx @ Wo^T + bo     [131072, 512]
    {
        dim3 grid(HID / 128, M_ROWS / 128);        // (4, 1024)
        sgemm_abt<<<grid, 256>>>(ctx_ptr, Wo, bo, out, M_ROWS, HID, HID);
    }
}

// round 13
// speedup vs baseline: 1.8273x; 1.8273x over previous
#include <cuda_runtime.h>
#include <cuda_bf16.h>
#include <cstdint>
#include <cstddef>

// Problem constants
#define B_SZ   4096
#define N_TOK  32
#define H_HEADS 8
#define D_HEAD 64
#define HID    512
#define M_ROWS (B_SZ * N_TOK)   // 131072
#define QKV_COLS (3 * HID)      // 1536

// ---------------------------------------------------------------------------
// Scratch (__device__ globals; allocation-free rule), 16B aligned.
// ---------------------------------------------------------------------------
__device__ __align__(16) float g_qkv[(size_t)M_ROWS * QKV_COLS];
__device__ __align__(16) __nv_bfloat16 g_xhi[(size_t)M_ROWS * HID];
__device__ __align__(16) __nv_bfloat16 g_xlo[(size_t)M_ROWS * HID];
__device__ __align__(16) __nv_bfloat16 g_chi[(size_t)M_ROWS * HID];
__device__ __align__(16) __nv_bfloat16 g_clo[(size_t)M_ROWS * HID];
__device__ __align__(16) __nv_bfloat16 g_w1hi[(size_t)QKV_COLS * HID];
__device__ __align__(16) __nv_bfloat16 g_w1lo[(size_t)QKV_COLS * HID];
__device__ __align__(16) __nv_bfloat16 g_w2hi[(size_t)HID * HID];
__device__ __align__(16) __nv_bfloat16 g_w2lo[(size_t)HID * HID];

__device__ __forceinline__ uint32_t smem_u32(const void* p) {
    uint32_t a;
    asm("{ .reg .u64 t; cvta.to.shared.u64 t, %1; cvt.u32.u64 %0, t; }"
        : "=r"(a) : "l"(p));
    return a;
}
__device__ __forceinline__ void cp_async16(uint32_t dst, const void* src) {
    asm volatile("cp.async.cg.shared.global [%0], [%1], 16;"
        :: "r"(dst), "l"(src) : "memory");
}

// ---------------------------------------------------------------------------
// f32 -> (bf16 hi, bf16 lo) split, 4 elems/thread
// ---------------------------------------------------------------------------
__global__ __launch_bounds__(256) void split_f32(
    const float* __restrict__ in, __nv_bfloat16* __restrict__ hi,
    __nv_bfloat16* __restrict__ lo, size_t n4)
{
    size_t i = (size_t)blockIdx.x * blockDim.x + threadIdx.x;
    if (i >= n4) return;
    float4 x = reinterpret_cast<const float4*>(in)[i];
    __nv_bfloat16 h[4], l[4];
    float xs[4] = {x.x, x.y, x.z, x.w};
#pragma unroll
    for (int j = 0; j < 4; j++) {
        h[j] = __float2bfloat16_rn(xs[j]);
        l[j] = __float2bfloat16_rn(xs[j] - __bfloat162float(h[j]));
    }
    reinterpret_cast<ushort4*>(hi)[i] = make_ushort4(
        __bfloat16_as_ushort(h[0]), __bfloat16_as_ushort(h[1]),
        __bfloat16_as_ushort(h[2]), __bfloat16_as_ushort(h[3]));
    reinterpret_cast<ushort4*>(lo)[i] = make_ushort4(
        __bfloat16_as_ushort(l[0]), __bfloat16_as_ushort(l[1]),
        __bfloat16_as_ushort(l[2]), __bfloat16_as_ushort(l[3]));
}

// ---------------------------------------------------------------------------
// GEMM via mma.sync m16n8k16 bf16, 3-pass hi/lo split:
//   C = Ahi@Bhi^T + Alo@Bhi^T + Ahi@Blo^T + bias   (fp32 accum/out)
// Block tile 128x128, 8 warps (2x4), warp tile 64x32, BK=32, double buffer.
// ---------------------------------------------------------------------------
#define GK    512
#define BKC   32
#define NCH   48            // 3 passes * 16 chunks of 32
#define PADR  40            // smem row stride in bf16 (80B): conflict-free ldmatrix

__global__ __launch_bounds__(256) void gemm_mma_x3(
    const __nv_bfloat16* __restrict__ Ahi, const __nv_bfloat16* __restrict__ Alo,
    const __nv_bfloat16* __restrict__ Bhi, const __nv_bfloat16* __restrict__ Blo,
    const float* __restrict__ bias, float* __restrict__ C, int Nfull)
{
    __shared__ __nv_bfloat16 As[2][128 * PADR];
    __shared__ __nv_bfloat16 Bs[2][128 * PADR];
    __shared__ float sbias[128];

    const int tid  = threadIdx.x;
    const int wid  = tid >> 5;
    const int lane = tid & 31;
    const int m_blk = blockIdx.y * 128;
    const int n_blk = blockIdx.x * 128;

    if (tid < 128) sbias[tid] = bias[n_blk + tid];

    const __nv_bfloat16* Aseg[3] = {Ahi, Alo, Ahi};
    const __nv_bfloat16* Bseg[3] = {Bhi, Bhi, Blo};

    const uint32_t as_base[2] = {smem_u32(As[0]), smem_u32(As[1])};
    const uint32_t bs_base[2] = {smem_u32(Bs[0]), smem_u32(Bs[1])};

    auto load_chunk = [&](int buf, int c) {
        int pass = c >> 4;
        int k0 = (c & 15) * BKC;
        const __nv_bfloat16* Ap = Aseg[pass] + (size_t)m_blk * GK + k0;
        const __nv_bfloat16* Bp = Bseg[pass] + (size_t)n_blk * GK + k0;
#pragma unroll
        for (int p = 0; p < 2; p++) {
            int id = tid + 256 * p;          // 0..511
            int r = id >> 2, c16 = id & 3;   // row, 16B unit (8 bf16)
            uint32_t soff = (uint32_t)r * (PADR * 2) + c16 * 16;
            cp_async16(as_base[buf] + soff, Ap + (size_t)r * GK + c16 * 8);
            cp_async16(bs_base[buf] + soff, Bp + (size_t)r * GK + c16 * 8);
        }
        asm volatile("cp.async.commit_group;" ::: "memory");
    };

    float acc[4][4][4];
#pragma unroll
    for (int i = 0; i < 4; i++)
#pragma unroll
        for (int j = 0; j < 4; j++)
#pragma unroll
            for (int e = 0; e < 4; e++) acc[i][j][e] = 0.f;

    const int wm = (wid & 1) * 64;     // warp m-offset in block
    const int wn = (wid >> 1) * 32;    // warp n-offset

    // ldmatrix lane addressing pieces (shared by A and B)
    const int lrow = (lane & 7) + ((lane >> 3) & 1) * 8;  // 0..15
    const int lcol = (lane >> 4) * 8;                     // 0 or 8

    load_chunk(0, 0);

    for (int c = 0; c < NCH; c++) {
        int b = c & 1;
        if (c + 1 < NCH) {
            load_chunk(b ^ 1, c + 1);
            asm volatile("cp.async.wait_group 1;" ::: "memory");
        } else {
            asm volatile("cp.async.wait_group 0;" ::: "memory");
        }
        __syncthreads();

#pragma unroll
        for (int ks = 0; ks < BKC; ks += 16) {
            uint32_t af[4][4], bf[2][4];
#pragma unroll
            for (int mt = 0; mt < 4; mt++) {
                uint32_t addr = as_base[b] +
                    ((uint32_t)(wm + mt * 16 + lrow) * PADR + ks + lcol) * 2;
                asm volatile(
                    "ldmatrix.sync.aligned.m8n8.x4.shared.b16 {%0,%1,%2,%3}, [%4];"
                    : "=r"(af[mt][0]), "=r"(af[mt][1]),
                      "=r"(af[mt][2]), "=r"(af[mt][3]) : "r"(addr));
            }
#pragma unroll
            for (int nt2 = 0; nt2 < 2; nt2++) {
                uint32_t addr = bs_base[b] +
                    ((uint32_t)(wn + nt2 * 16 + lrow) * PADR + ks + lcol) * 2;
                asm volatile(
                    "ldmatrix.sync.aligned.m8n8.x4.shared.b16 {%0,%1,%2,%3}, [%4];"
                    : "=r"(bf[nt2][0]), "=r"(bf[nt2][1]),
                      "=r"(bf[nt2][2]), "=r"(bf[nt2][3]) : "r"(addr));
            }
#pragma unroll
            for (int mt = 0; mt < 4; mt++)
#pragma unroll
                for (int nt = 0; nt < 4; nt++) {
                    uint32_t b0 = bf[nt >> 1][nt & 1];
                    uint32_t b1 = bf[nt >> 1][(nt & 1) + 2];
                    asm volatile(
                        "mma.sync.aligned.m16n8k16.row.col.f32.bf16.bf16.f32 "
                        "{%0,%1,%2,%3}, {%4,%5,%6,%7}, {%8,%9}, {%0,%1,%2,%3};"
                        : "+f"(acc[mt][nt][0]), "+f"(acc[mt][nt][1]),
                          "+f"(acc[mt][nt][2]), "+f"(acc[mt][nt][3])
                        : "r"(af[mt][0]), "r"(af[mt][1]),
                          "r"(af[mt][2]), "r"(af[mt][3]),
                          "r"(b0), "r"(b1));
                }
        }
        __syncthreads();
    }

    // Epilogue: c0,c1 -> (m = t/4, n = 2*(t%4)), c2,c3 -> m+8
    const int erow = lane >> 2;
    const int ecol = (lane & 3) * 2;
#pragma unroll
    for (int mt = 0; mt < 4; mt++) {
#pragma unroll
        for (int nt = 0; nt < 4; nt++) {
            int colL = wn + nt * 8 + ecol;
            float bv0 = sbias[colL], bv1 = sbias[colL + 1];
            size_t r0 = (size_t)(m_blk + wm + mt * 16 + erow);
            float2 v0 = make_float2(acc[mt][nt][0] + bv0, acc[mt][nt][1] + bv1);
            float2 v1 = make_float2(acc[mt][nt][2] + bv0, acc[mt][nt][3] + bv1);
            *reinterpret_cast<float2*>(&C[r0 * Nfull + n_blk + colL]) = v0;
            *reinterpret_cast<float2*>(&C[(r0 + 8) * Nfull + n_blk + colL]) = v1;
        }
    }
}

// ---------------------------------------------------------------------------
// Attention: one block per (b, h). fp32 qkv in; attn probs (f32) + ctx as
// bf16 hi/lo out. Mask dtype detection proven in R8.
// ---------------------------------------------------------------------------
__global__ __launch_bounds__(128) void attn_kernel(
    const float* __restrict__ qkv, const void* __restrict__ mask_raw,
    float* __restrict__ attn_out,
    __nv_bfloat16* __restrict__ chi, __nv_bfloat16* __restrict__ clo)
{
    const int bh = blockIdx.x;
    const int b = bh >> 3, h = bh & 7;

    __shared__ float q[32][64], k[32][64], v[32][64];
    __shared__ float s[32][33];
    __shared__ unsigned char msk[1024];
    __shared__ int mode;

    const int tid = threadIdx.x;

    if (tid == 0) {
        const unsigned char* m8 = (const unsigned char*)mask_raw;
        const int* m32 = (const int*)mask_raw;
        bool u8ok = true;
#pragma unroll
        for (int i = 0; i < 32; i++) u8ok &= (m8[i * 33] == 1);
        if (u8ok) { mode = 0; }
        else {
            bool i32ok = true;
#pragma unroll
            for (int i = 0; i < 8; i++) i32ok &= (m32[i * 33] == 1);
            mode = i32ok ? 1 : 2;
        }
    }

    const float* base = qkv + (size_t)b * (N_TOK * QKV_COLS) + h * D_HEAD;
    for (int i = tid; i < 512; i += 128) {
        int n = i >> 4, d4 = (i & 15) * 4;
        const float* rp = base + (size_t)n * QKV_COLS + d4;
        *reinterpret_cast<float4*>(&q[n][d4]) = *reinterpret_cast<const float4*>(rp);
        *reinterpret_cast<float4*>(&k[n][d4]) = *reinterpret_cast<const float4*>(rp + HID);
        *reinterpret_cast<float4*>(&v[n][d4]) = *reinterpret_cast<const float4*>(rp + 2 * HID);
    }
    __syncthreads();

    {
        int md = mode;
        const unsigned char* m8 = (const unsigned char*)mask_raw;
        const int* m32 = (const int*)mask_raw;
        const float* mf = (const float*)mask_raw;
        for (int i = tid; i < 1024; i += 128) {
            unsigned char mv;
            if (md == 0)      mv = (m8[i] != 0);
            else if (md == 1) mv = (m32[i] != 0);
            else              mv = (mf[i] != 0.0f);
            msk[i] = mv;
        }
    }
    __syncthreads();

    for (int e = tid; e < 1024; e += 128) {
        int i = e >> 5, j = e & 31;
        float accv = 0.f;
#pragma unroll
        for (int d = 0; d < 64; d++) accv = fmaf(q[i][d], k[j][d], accv);
        s[i][j] = msk[e] ? accv * 0.125f : -1e9f;
    }
    __syncthreads();

    if (tid < 32) {
        int i = tid;
        float mx = -3.0e38f;
#pragma unroll
        for (int j = 0; j < 32; j++) mx = fmaxf(mx, s[i][j]);
        float p[32];
        float sum = 0.f;
#pragma unroll
        for (int j = 0; j < 32; j++) { p[j] = expf(s[i][j] - mx); sum += p[j]; }
        float inv = 1.0f / sum;
#pragma unroll
        for (int j = 0; j < 32; j++) s[i][j] = p[j] * inv;
    }
    __syncthreads();

    float* aout = attn_out + (size_t)bh * 1024;
    for (int e = tid; e < 1024; e += 128) aout[e] = s[e >> 5][e & 31];

    size_t coff = (size_t)b * (N_TOK * HID) + h * D_HEAD;
    for (int e = tid; e < 2048; e += 128) {
        int n = e >> 6, d = e & 63;
        float accv = 0.f;
#pragma unroll
        for (int m = 0; m < 32; m++) accv = fmaf(s[n][m], v[m][d], accv);
        __nv_bfloat16 hv = __float2bfloat16_rn(accv);
        __nv_bfloat16 lv = __float2bfloat16_rn(accv - __bfloat162float(hv));
        size_t idx = coff + (size_t)n * HID + d;
        chi[idx] = hv;
        clo[idx] = lv;
    }
}

// ---------------------------------------------------------------------------
// Inputs: module_states f32 [4096,32,512], sparse_mask [32,32] (detected),
// Wqkv f32 [1536,512], bqkv [1536], Wo f32 [512,512], bo [512]
// Output: output [4096,32,512] f32, then attn [4096,8,32,32] f32.
// ---------------------------------------------------------------------------
extern "C" void kernel_launch(void* const* d_in, const int* in_sizes, int n_in,
                              void* d_out, int out_size)
{
    const float* x    = (const float*)d_in[0];
    const void*  mask = d_in[1];
    const float* Wqkv = (const float*)d_in[2];
    const float* bqkv = (const float*)d_in[3];
    const float* Wo   = (const float*)d_in[4];
    const float* bo   = (const float*)d_in[5];

    float* out  = (float*)d_out;
    float* attn = out + (size_t)M_ROWS * HID;

    float *qkv_p;
    __nv_bfloat16 *xhi, *xlo, *chi, *clo, *w1hi, *w1lo, *w2hi, *w2lo;
    cudaGetSymbolAddress((void**)&qkv_p, g_qkv);
    cudaGetSymbolAddress((void**)&xhi, g_xhi);
    cudaGetSymbolAddress((void**)&xlo, g_xlo);
    cudaGetSymbolAddress((void**)&chi, g_chi);
    cudaGetSymbolAddress((void**)&clo, g_clo);
    cudaGetSymbolAddress((void**)&w1hi, g_w1hi);
    cudaGetSymbolAddress((void**)&w1lo, g_w1lo);
    cudaGetSymbolAddress((void**)&w2hi, g_w2hi);
    cudaGetSymbolAddress((void**)&w2lo, g_w2lo);

    // 0) split inputs into bf16 hi/lo
    {
        size_t n4 = (size_t)M_ROWS * HID / 4;
        split_f32<<<(unsigned)((n4 + 255) / 256), 256>>>(x, xhi, xlo, n4);
        size_t w1 = (size_t)QKV_COLS * HID / 4;
        split_f32<<<(unsigned)((w1 + 255) / 256), 256>>>(Wqkv, w1hi, w1lo, w1);
        size_t w2 = (size_t)HID * HID / 4;
        split_f32<<<(unsigned)((w2 + 255) / 256), 256>>>(Wo, w2hi, w2lo, w2);
    }

    // 1) QKV = X @ Wqkv^T + bqkv
    {
        dim3 grid(QKV_COLS / 128, M_ROWS / 128);   // (12, 1024)
        gemm_mma_x3<<<grid, 256>>>(xhi, xlo, w1hi, w1lo, bqkv, qkv_p, QKV_COLS);
    }

    // 2) attention per (b, h); ctx emitted as bf16 hi/lo
    attn_kernel<<<B_SZ * H_HEADS, 128>>>(qkv_p, mask, attn, chi, clo);

    // 3) output = ctx @ Wo^T + bo
    {
        dim3 grid(HID / 128, M_ROWS / 128);        // (4, 1024)
        gemm_mma_x3<<<grid, 256>>>(chi, clo, w2hi, w2lo, bo, out, HID);
    }
}